// round 8
// baseline (speedup 1.0000x reference)
#include <cuda_runtime.h>
#include <float.h>
#include <math.h>

#define NQ 4096
#define NS 1600
#define DIM 1024
#define NC 64
#define KNN 12
#define MAX_ITER 50
#define EPS_CONV 1e-4f

// ------------------------------ scratch (device globals; no allocs) -----------------
__device__ float g_protos[NC * DIM];
__device__ float g_pnorm[NC];
__device__ float g_qnorm[NQ];
__device__ float g_D[(size_t)NQ * NQ];          // SQUARED distances (clamped >= 0)
__device__ int   g_nbrs[NQ * KNN];
__device__ float g_wdist[NQ * KNN];             // sqrt distances to neighbors
__device__ float g_sigma[NQ];
__device__ int   g_deg[NQ];
__device__ int   g_rowptr[NQ + 1];
__device__ int   g_cursor[NQ];
__device__ int   g_col[NQ * 2 * KNN];
__device__ float g_val[NQ * 2 * KNN];
__device__ float g_Dinv[NQ];
__device__ float g_a[NQ * NC];
__device__ float g_d2[NQ];
__device__ float g_coef[NQ];
__device__ float g_med2;
__device__ float g_Y[2][NQ * NC];
__device__ unsigned g_diff[MAX_ITER];
__device__ int   g_done;
__device__ int   g_ans;
__device__ int   g_mode;   // label encoding: 0 = int32, 1 = int64, 2 = float32

// ------------------------------ helpers ---------------------------------------------
__device__ __forceinline__ float warpSumf(float v) {
#pragma unroll
    for (int o = 16; o > 0; o >>= 1) v += __shfl_xor_sync(0xffffffffu, v, o);
    return v;
}
__device__ __forceinline__ float warpMaxf(float v) {
#pragma unroll
    for (int o = 16; o > 0; o >>= 1) v = fmaxf(v, __shfl_xor_sync(0xffffffffu, v, o));
    return v;
}

// ------------------------------ init + 3-way label encoding detection ---------------
__global__ void init_kernel(const unsigned* __restrict__ ys_raw) {
    int idx = blockIdx.x * blockDim.x + threadIdx.x;
    if (idx < NQ) g_deg[idx] = 0;
    if (idx < MAX_ITER) g_diff[idx] = 0u;
    if (idx == 0) {
        g_done = 0;
        g_ans = 0;
        // int64 signature: (label, 0) word pairs, label in [0,64)
        int v64 = 1;
        for (int s = 0; s < 128; s++) {
            unsigned lo = ys_raw[2 * s];
            unsigned hi = ys_raw[2 * s + 1];
            if (hi != 0u || lo >= 64u) { v64 = 0; break; }
        }
        if (v64) { g_mode = 1; return; }
        // int32 signature: every word in [0,64)
        int v32 = 1;
        for (int s = 0; s < 256; s++)
            if (ys_raw[s] >= 64u) { v32 = 0; break; }
        if (v32) { g_mode = 0; return; }
        // float32 signature: integral floats in [0,64)
        int vf = 1;
        for (int s = 0; s < 256; s++) {
            float f = __uint_as_float(ys_raw[s]);
            if (!(f >= 0.0f && f < 64.0f && f == floorf(f))) { vf = 0; break; }
        }
        g_mode = vf ? 2 : 0;
    }
}

// ------------------------------ prototypes (deterministic, no atomics) --------------
__global__ void __launch_bounds__(256) protos_kernel(const float* __restrict__ fs,
                                                     const void* __restrict__ ys) {
    int c = blockIdx.x;
    int tid = threadIdx.x;
    int mode = g_mode;
    const int* ys32 = (const int*)ys;
    const long long* ys64 = (const long long*)ys;
    const float* ysf = (const float*)ys;
    float acc[4] = {0.f, 0.f, 0.f, 0.f};
    int cnt = 0;
    for (int s = 0; s < NS; s++) {
        int lbl;
        if (mode == 1)      lbl = (int)ys64[s];
        else if (mode == 2) lbl = (int)ysf[s];
        else                lbl = ys32[s];
        if (lbl == c) {
            cnt++;
            const float* row = fs + (size_t)s * DIM;
#pragma unroll
            for (int u = 0; u < 4; u++) acc[u] += row[tid + u * 256];
        }
    }
    float cden = fmaxf((float)cnt, 1.0f);
    float psq = 0.f;
#pragma unroll
    for (int u = 0; u < 4; u++) {
        float p = acc[u] / cden;
        g_protos[c * DIM + tid + u * 256] = p;
        psq += p * p;
    }
    __shared__ float red[256];
    red[tid] = psq;
    __syncthreads();
    for (int o = 128; o > 0; o >>= 1) {
        if (tid < o) red[tid] += red[tid + o];
        __syncthreads();
    }
    if (tid == 0) g_pnorm[c] = red[0];
}

// ------------------------------ query norms -----------------------------------------
__global__ void qnorm_kernel(const float* __restrict__ q) {
    int warp = threadIdx.x >> 5;
    int lane = threadIdx.x & 31;
    int row = blockIdx.x * 8 + warp;
    if (row >= NQ) return;
    const float* r = q + (size_t)row * DIM;
    float s = 0.f;
    for (int d = lane; d < DIM; d += 32) s += r[d] * r[d];
    s = warpSumf(s);
    if (lane == 0) g_qnorm[row] = s;
}

// ------------------------------ distance GEMM (stores clamped SQUARED dist) ---------
__global__ void __launch_bounds__(256) gemm_dist_kernel(const float* __restrict__ q) {
    int bx = blockIdx.x, by = blockIdx.y;
    if (by > bx) return;
    __shared__ __align__(16) float As[32][128];
    __shared__ __align__(16) float Bs[32][128];
    int tid = threadIdx.x;
    int lr = tid & 31;
    int lc = (tid >> 5) << 2;
    int tx = tid & 15, ty = tid >> 4;
    float acc[8][8];
#pragma unroll
    for (int m = 0; m < 8; m++)
#pragma unroll
        for (int n = 0; n < 8; n++) acc[m][n] = 0.f;

    const float* Ab = q + (size_t)(bx * 128) * DIM;
    const float* Bb = q + (size_t)(by * 128) * DIM;

    for (int k0 = 0; k0 < DIM; k0 += 32) {
#pragma unroll
        for (int p = 0; p < 4; p++) {
            int r = p * 32 + lr;
            float4 va = *(const float4*)(Ab + (size_t)r * DIM + k0 + lc);
            As[lc + 0][r] = va.x; As[lc + 1][r] = va.y; As[lc + 2][r] = va.z; As[lc + 3][r] = va.w;
            float4 vb = *(const float4*)(Bb + (size_t)r * DIM + k0 + lc);
            Bs[lc + 0][r] = vb.x; Bs[lc + 1][r] = vb.y; Bs[lc + 2][r] = vb.z; Bs[lc + 3][r] = vb.w;
        }
        __syncthreads();
#pragma unroll
        for (int kk = 0; kk < 32; kk++) {
            float a[8], b[8];
            *(float4*)&a[0] = *(const float4*)&As[kk][ty * 8];
            *(float4*)&a[4] = *(const float4*)&As[kk][ty * 8 + 4];
            *(float4*)&b[0] = *(const float4*)&Bs[kk][tx * 8];
            *(float4*)&b[4] = *(const float4*)&Bs[kk][tx * 8 + 4];
#pragma unroll
            for (int m = 0; m < 8; m++)
#pragma unroll
                for (int n = 0; n < 8; n++) acc[m][n] += a[m] * b[n];
        }
        __syncthreads();
    }

    int gi0 = bx * 128 + ty * 8;
    int gj0 = by * 128 + tx * 8;
    float qi[8], qj[8];
#pragma unroll
    for (int m = 0; m < 8; m++) qi[m] = g_qnorm[gi0 + m];
#pragma unroll
    for (int n = 0; n < 8; n++) qj[n] = g_qnorm[gj0 + n];
#pragma unroll
    for (int m = 0; m < 8; m++) {
#pragma unroll
        for (int n = 0; n < 8; n++) {
            float dv = fmaxf(qi[m] + qj[n] - 2.0f * acc[m][n], 0.0f);
            g_D[(size_t)(gi0 + m) * NQ + (gj0 + n)] = dv;
            g_D[(size_t)(gj0 + n) * NQ + (gi0 + m)] = dv;
        }
    }
}

// ------------------------------ top-13 per row (block per row, 13 passes) -----------
__global__ void __launch_bounds__(256) topk_kernel() {
    int row = blockIdx.x;
    int tid = threadIdx.x;
    __shared__ float s[NQ];
    __shared__ unsigned long long red[256];
    const float* drow = &g_D[(size_t)row * NQ];
    for (int j = tid; j < NQ; j += 256) s[j] = sqrtf(drow[j]);
    __syncthreads();
    for (int sel = 0; sel < KNN + 1; sel++) {
        unsigned long long best = ~0ull;
        for (int j = tid; j < NQ; j += 256) {
            unsigned long long key =
                ((unsigned long long)__float_as_uint(s[j]) << 32) | (unsigned)j;
            best = best < key ? best : key;
        }
        red[tid] = best;
        __syncthreads();
        for (int o = 128; o > 0; o >>= 1) {
            if (tid < o) red[tid] = red[tid] < red[tid + o] ? red[tid] : red[tid + o];
            __syncthreads();
        }
        if (tid == 0) {
            unsigned long long b = red[0];
            int idx = (int)(b & 0xffffffffull);
            float val = __uint_as_float((unsigned)(b >> 32));
            if (sel >= 1) {
                g_nbrs[row * KNN + sel - 1] = idx;
                g_wdist[row * KNN + sel - 1] = val;
            }
            if (sel == KNN) g_sigma[row] = val + 1e-8f;
            s[idx] = FLT_MAX;
        }
        __syncthreads();
    }
}

// ------------------------------ CSR build -------------------------------------------
__global__ void deg_kernel() {
    int idx = blockIdx.x * blockDim.x + threadIdx.x;
    if (idx >= NQ * KNN) return;
    int i = idx / KNN;
    int j = g_nbrs[idx];
    atomicAdd(&g_deg[i], 1);
    atomicAdd(&g_deg[j], 1);
}

__global__ void __launch_bounds__(1024) scan_kernel() {
    __shared__ int sh[1024];
    int tid = threadIdx.x;
    int b = tid * 4;
    int d0 = g_deg[b], d1 = g_deg[b + 1], d2 = g_deg[b + 2], d3 = g_deg[b + 3];
    int s = d0 + d1 + d2 + d3;
    sh[tid] = s;
    __syncthreads();
    for (int off = 1; off < 1024; off <<= 1) {
        int v = (tid >= off) ? sh[tid - off] : 0;
        __syncthreads();
        sh[tid] += v;
        __syncthreads();
    }
    int excl = (tid == 0) ? 0 : sh[tid - 1];
    g_rowptr[b] = excl;     g_cursor[b] = excl;     excl += d0;
    g_rowptr[b + 1] = excl; g_cursor[b + 1] = excl; excl += d1;
    g_rowptr[b + 2] = excl; g_cursor[b + 2] = excl; excl += d2;
    g_rowptr[b + 3] = excl; g_cursor[b + 3] = excl; excl += d3;
    if (tid == 1023) g_rowptr[NQ] = excl;
}

__global__ void fill_kernel() {
    int idx = blockIdx.x * blockDim.x + threadIdx.x;
    if (idx >= NQ * KNN) return;
    int i = idx / KNN;
    int j = g_nbrs[idx];
    float w = expf(-g_wdist[idx] / (g_sigma[i] * g_sigma[j]));
    float h = 0.5f * w;
    int p1 = atomicAdd(&g_cursor[i], 1);
    g_col[p1] = j; g_val[p1] = h;
    int p2 = atomicAdd(&g_cursor[j], 1);
    g_col[p2] = i; g_val[p2] = h;
}

__global__ void __launch_bounds__(64) sortdinv_kernel() {
    int row = blockIdx.x * blockDim.x + threadIdx.x;
    if (row >= NQ) return;
    int s = g_rowptr[row], e = g_rowptr[row + 1];
    for (int i = s + 1; i < e; i++) {
        int c = g_col[i]; float v = g_val[i];
        int j = i - 1;
        while (j >= s && g_col[j] > c) {
            g_col[j + 1] = g_col[j]; g_val[j + 1] = g_val[j]; j--;
        }
        g_col[j + 1] = c; g_val[j + 1] = v;
    }
    float sum = 0.f;
    for (int i = s; i < e; i++) sum += g_val[i];
    g_Dinv[row] = 1.0f / (sum + 1e-8f);
}

// ------------------------------ a = sqdist(q, protos), d2 = a.min(1) ----------------
__global__ void __launch_bounds__(256) a_kernel(const float* __restrict__ q) {
    int row = blockIdx.x;
    int tid = threadIdx.x;
    int warp = tid >> 5, lane = tid & 31;
    __shared__ float qr[DIM];
    for (int j = tid; j < DIM; j += 256) qr[j] = q[(size_t)row * DIM + j];
    __syncthreads();
    float qn = g_qnorm[row];
    float lmin = FLT_MAX;
    for (int p = warp; p < NC; p += 8) {
        float dot = 0.f;
        const float* pr = &g_protos[p * DIM];
        for (int d = lane; d < DIM; d += 32) dot += qr[d] * pr[d];
        dot = warpSumf(dot);
        float av = fmaxf(qn + g_pnorm[p] - 2.0f * dot, 0.0f);
        if (lane == 0) g_a[row * NC + p] = av;
        lmin = fminf(lmin, av);
    }
    __shared__ float wmin[8];
    if (lane == 0) wmin[warp] = lmin;
    __syncthreads();
    if (tid == 0) {
        float m = wmin[0];
        for (int w = 1; w < 8; w++) m = fminf(m, wmin[w]);
        g_d2[row] = m;
    }
}

// ------------------------------ median via bitonic sort -----------------------------
__global__ void __launch_bounds__(1024) median_kernel() {
    __shared__ float sd[NQ];
    int tid = threadIdx.x;
    for (int j = tid; j < NQ; j += 1024) sd[j] = sqrtf(g_d2[j]);
    __syncthreads();
    for (int k = 2; k <= NQ; k <<= 1) {
        for (int j = k >> 1; j > 0; j >>= 1) {
            for (int i = tid; i < NQ; i += 1024) {
                int l = i ^ j;
                if (l > i) {
                    bool asc = ((i & k) == 0);
                    float a = sd[i], b = sd[l];
                    if ((a > b) == asc) { sd[i] = b; sd[l] = a; }
                }
            }
            __syncthreads();
        }
    }
    if (tid == 0) {
        float med = 0.5f * (sd[NQ / 2 - 1] + sd[NQ / 2]);
        g_med2 = 2.0f * med * med + 1e-8f;
    }
}

__global__ void coef_kernel() {
    int idx = blockIdx.x * blockDim.x + threadIdx.x;
    if (idx < NQ) g_coef[idx] = expf(-g_d2[idx] / g_med2) * g_Dinv[idx];
}

// ------------------------------ y0 = softmax(-a) ------------------------------------
__global__ void __launch_bounds__(128) y0_kernel() {
    int warp = threadIdx.x >> 5, lane = threadIdx.x & 31;
    int row = blockIdx.x * 4 + warp;
    float l0 = -g_a[row * NC + lane];
    float l1 = -g_a[row * NC + lane + 32];
    float m = warpMaxf(fmaxf(l0, l1));
    float e0 = expf(l0 - m), e1 = expf(l1 - m);
    float ss = warpSumf(e0 + e1);
    g_Y[0][row * NC + lane] = e0 / ss;
    g_Y[0][row * NC + lane + 32] = e1 / ss;
}

// ------------------------------ one MM iteration (SpMV + softmax + diff) ------------
__global__ void __launch_bounds__(128) step_kernel(int t) {
    if (g_done) return;
    const float* __restrict__ yin = g_Y[t & 1];
    float* __restrict__ yout = g_Y[(t + 1) & 1];
    int warp = threadIdx.x >> 5, lane = threadIdx.x & 31;
    int row = blockIdx.x * 4 + warp;
    int s = g_rowptr[row], e = g_rowptr[row + 1];
    float acc0 = 0.f, acc1 = 0.f;
    for (int k = s; k < e; k++) {
        int c = g_col[k];
        float v = g_val[k];
        acc0 += v * yin[c * NC + lane];
        acc1 += v * yin[c * NC + lane + 32];
    }
    float cf = g_coef[row];
    float l0 = cf * acc0 - g_a[row * NC + lane];
    float l1 = cf * acc1 - g_a[row * NC + lane + 32];
    float m = warpMaxf(fmaxf(l0, l1));
    float e0 = expf(l0 - m), e1 = expf(l1 - m);
    float ss = warpSumf(e0 + e1);
    float y0n = e0 / ss, y1n = e1 / ss;
    float d0 = fabsf(y0n - yin[row * NC + lane]);
    float d1 = fabsf(y1n - yin[row * NC + lane + 32]);
    yout[row * NC + lane] = y0n;
    yout[row * NC + lane + 32] = y1n;
    float dmx = warpMaxf(fmaxf(d0, d1));
    __shared__ unsigned sd[4];
    if (lane == 0) sd[warp] = __float_as_uint(dmx);
    __syncthreads();
    if (threadIdx.x == 0) {
        unsigned mx = max(max(sd[0], sd[1]), max(sd[2], sd[3]));
        atomicMax(&g_diff[t], mx);
    }
}

__global__ void check_kernel(int t) {
    if (g_done) return;
    if (__uint_as_float(g_diff[t]) < EPS_CONV) {
        g_done = 1;
        g_ans = t & 1;   // return y_t
    }
}

// ------------------------------ argmax: store FLOAT32 values ------------------------
__global__ void __launch_bounds__(128) argmax_kernel(float* __restrict__ out) {
    int warp = threadIdx.x >> 5, lane = threadIdx.x & 31;
    int row = blockIdx.x * 4 + warp;
    const float* y = g_Y[g_ans];
    float v0 = y[row * NC + lane];
    float v1 = y[row * NC + lane + 32];
    float bv; int bi;
    if (v0 >= v1) { bv = v0; bi = lane; } else { bv = v1; bi = lane + 32; }
#pragma unroll
    for (int o = 16; o > 0; o >>= 1) {
        float ov = __shfl_xor_sync(0xffffffffu, bv, o);
        int oi = __shfl_xor_sync(0xffffffffu, bi, o);
        if (ov > bv || (ov == bv && oi < bi)) { bv = ov; bi = oi; }
    }
    if (lane == 0) out[row] = (float)bi;
}

// ------------------------------ launch ----------------------------------------------
extern "C" void kernel_launch(void* const* d_in, const int* in_sizes, int n_in,
                              void* d_out, int out_size) {
    // Rank-based identification: smallest -> y_s, middle -> feat_s, largest -> feat_q.
    int i0 = 0, i1 = 1, i2 = 2;
    if (n_in >= 3) {
        int idxs[3] = {0, 1, 2};
        for (int a = 0; a < 2; a++)
            for (int b = a + 1; b < 3; b++)
                if ((long long)in_sizes[idxs[b]] < (long long)in_sizes[idxs[a]]) {
                    int tmp = idxs[a]; idxs[a] = idxs[b]; idxs[b] = tmp;
                }
        i0 = idxs[0]; i1 = idxs[1]; i2 = idxs[2];
    }
    const void*  y_s    = d_in[i0];
    const float* feat_s = (const float*)d_in[i1];
    const float* feat_q = (const float*)d_in[i2];

    init_kernel<<<16, 256>>>((const unsigned*)y_s);
    protos_kernel<<<NC, 256>>>(feat_s, y_s);
    qnorm_kernel<<<NQ / 8, 256>>>(feat_q);
    dim3 gg(NQ / 128, NQ / 128);
    gemm_dist_kernel<<<gg, 256>>>(feat_q);
    topk_kernel<<<NQ, 256>>>();
    deg_kernel<<<(NQ * KNN) / 256, 256>>>();
    scan_kernel<<<1, 1024>>>();
    fill_kernel<<<(NQ * KNN) / 256, 256>>>();
    sortdinv_kernel<<<NQ / 64, 64>>>();
    a_kernel<<<NQ, 256>>>(feat_q);
    median_kernel<<<1, 1024>>>();
    coef_kernel<<<16, 256>>>();
    y0_kernel<<<NQ / 4, 128>>>();
    for (int t = 0; t < MAX_ITER; t++) {
        step_kernel<<<NQ / 4, 128>>>(t);
        check_kernel<<<1, 1>>>(t);
    }
    argmax_kernel<<<NQ / 4, 128>>>((float*)d_out);
}

// round 9
// speedup vs baseline: 3.6142x; 3.6142x over previous
#include <cuda_runtime.h>
#include <float.h>
#include <math.h>

#define NQ 4096
#define NS 1600
#define DIM 1024
#define NC 64
#define KNN 12
#define MAX_ITER 50
#define EPS_CONV 1e-4f
#define IBLK 128                 // persistent blocks (<= SM count, all co-resident)
#define RPB (NQ / IBLK)          // 32 rows per block

// ------------------------------ scratch (device globals; no allocs) -----------------
__device__ float g_protos[NC * DIM];
__device__ float g_pnorm[NC];
__device__ float g_qnorm[NQ];
__device__ float g_D[(size_t)NQ * NQ];          // SQUARED distances (clamped >= 0)
__device__ int   g_nbrs[NQ * KNN];
__device__ float g_wdist[NQ * KNN];             // sqrt distances to neighbors
__device__ float g_sigma[NQ];
__device__ int   g_rowptr[NQ + 1];
__device__ int   g_col[NQ * 2 * KNN];
__device__ float g_val[NQ * 2 * KNN];
__device__ float g_Dinv[NQ];
__device__ float g_a[NQ * NC];
__device__ float g_d2[NQ];
__device__ float g_coef[NQ];
__device__ float g_Y[2][NQ * NC];
__device__ int   g_flag[MAX_ITER];              // 1 = not converged at step t
__device__ int   g_mode;                        // labels: 0=int32, 1=int64, 2=float32
__device__ int   g_barc;                        // grid barrier counter
__device__ volatile int g_bars;                 // grid barrier sense

// ------------------------------ helpers ---------------------------------------------
__device__ __forceinline__ float warpSumf(float v) {
#pragma unroll
    for (int o = 16; o > 0; o >>= 1) v += __shfl_xor_sync(0xffffffffu, v, o);
    return v;
}
__device__ __forceinline__ float warpMaxf(float v) {
#pragma unroll
    for (int o = 16; o > 0; o >>= 1) v = fmaxf(v, __shfl_xor_sync(0xffffffffu, v, o));
    return v;
}

// ------------------------------ init + 3-way label encoding detection ---------------
__global__ void __launch_bounds__(256) init_kernel(const unsigned* __restrict__ ys_raw) {
    __shared__ unsigned sy[256];
    int tid = threadIdx.x;
    sy[tid] = ys_raw[tid];
    if (tid < MAX_ITER) g_flag[tid] = 0;
    if (tid == 0) { g_barc = 0; g_bars = 0; }
    __syncthreads();
    if (tid == 0) {
        // int64 signature: (label, 0) word pairs, label in [0,64)
        int v64 = 1;
        for (int s = 0; s < 128; s++) {
            unsigned lo = sy[2 * s], hi = sy[2 * s + 1];
            if (hi != 0u || lo >= 64u) { v64 = 0; break; }
        }
        if (v64) { g_mode = 1; return; }
        // int32 signature: every word in [0,64)
        int v32 = 1;
        for (int s = 0; s < 256; s++)
            if (sy[s] >= 64u) { v32 = 0; break; }
        if (v32) { g_mode = 0; return; }
        // float32 signature: integral floats in [0,64)
        int vf = 1;
        for (int s = 0; s < 256; s++) {
            float f = __uint_as_float(sy[s]);
            if (!(f >= 0.0f && f < 64.0f && f == floorf(f))) { vf = 0; break; }
        }
        g_mode = vf ? 2 : 0;
    }
}

// ------------------------------ prototypes (labels staged in smem) ------------------
__global__ void __launch_bounds__(256) protos_kernel(const float* __restrict__ fs,
                                                     const void* __restrict__ ys) {
    __shared__ int slbl[NS];
    int c = blockIdx.x;
    int tid = threadIdx.x;
    int mode = g_mode;
    for (int s = tid; s < NS; s += 256) {
        int lbl;
        if (mode == 1)      lbl = (int)((const long long*)ys)[s];
        else if (mode == 2) lbl = (int)((const float*)ys)[s];
        else                lbl = ((const int*)ys)[s];
        slbl[s] = lbl;
    }
    __syncthreads();
    float acc[4] = {0.f, 0.f, 0.f, 0.f};
    int cnt = 0;
    for (int s = 0; s < NS; s++) {
        if (slbl[s] == c) {
            cnt++;
            const float* row = fs + (size_t)s * DIM;
#pragma unroll
            for (int u = 0; u < 4; u++) acc[u] += row[tid + u * 256];
        }
    }
    float cden = fmaxf((float)cnt, 1.0f);
    float psq = 0.f;
#pragma unroll
    for (int u = 0; u < 4; u++) {
        float p = acc[u] / cden;
        g_protos[c * DIM + tid + u * 256] = p;
        psq += p * p;
    }
    __shared__ float red[256];
    red[tid] = psq;
    __syncthreads();
    for (int o = 128; o > 0; o >>= 1) {
        if (tid < o) red[tid] += red[tid + o];
        __syncthreads();
    }
    if (tid == 0) g_pnorm[c] = red[0];
}

// ------------------------------ query norms -----------------------------------------
__global__ void qnorm_kernel(const float* __restrict__ q) {
    int warp = threadIdx.x >> 5;
    int lane = threadIdx.x & 31;
    int row = blockIdx.x * 8 + warp;
    if (row >= NQ) return;
    const float* r = q + (size_t)row * DIM;
    float s = 0.f;
    for (int d = lane; d < DIM; d += 32) s += r[d] * r[d];
    s = warpSumf(s);
    if (lane == 0) g_qnorm[row] = s;
}

// ------------------------------ distance GEMM (unchanged — exact) -------------------
__global__ void __launch_bounds__(256) gemm_dist_kernel(const float* __restrict__ q) {
    int bx = blockIdx.x, by = blockIdx.y;
    if (by > bx) return;
    __shared__ __align__(16) float As[32][128];
    __shared__ __align__(16) float Bs[32][128];
    int tid = threadIdx.x;
    int lr = tid & 31;
    int lc = (tid >> 5) << 2;
    int tx = tid & 15, ty = tid >> 4;
    float acc[8][8];
#pragma unroll
    for (int m = 0; m < 8; m++)
#pragma unroll
        for (int n = 0; n < 8; n++) acc[m][n] = 0.f;

    const float* Ab = q + (size_t)(bx * 128) * DIM;
    const float* Bb = q + (size_t)(by * 128) * DIM;

    for (int k0 = 0; k0 < DIM; k0 += 32) {
#pragma unroll
        for (int p = 0; p < 4; p++) {
            int r = p * 32 + lr;
            float4 va = *(const float4*)(Ab + (size_t)r * DIM + k0 + lc);
            As[lc + 0][r] = va.x; As[lc + 1][r] = va.y; As[lc + 2][r] = va.z; As[lc + 3][r] = va.w;
            float4 vb = *(const float4*)(Bb + (size_t)r * DIM + k0 + lc);
            Bs[lc + 0][r] = vb.x; Bs[lc + 1][r] = vb.y; Bs[lc + 2][r] = vb.z; Bs[lc + 3][r] = vb.w;
        }
        __syncthreads();
#pragma unroll
        for (int kk = 0; kk < 32; kk++) {
            float a[8], b[8];
            *(float4*)&a[0] = *(const float4*)&As[kk][ty * 8];
            *(float4*)&a[4] = *(const float4*)&As[kk][ty * 8 + 4];
            *(float4*)&b[0] = *(const float4*)&Bs[kk][tx * 8];
            *(float4*)&b[4] = *(const float4*)&Bs[kk][tx * 8 + 4];
#pragma unroll
            for (int m = 0; m < 8; m++)
#pragma unroll
                for (int n = 0; n < 8; n++) acc[m][n] += a[m] * b[n];
        }
        __syncthreads();
    }

    int gi0 = bx * 128 + ty * 8;
    int gj0 = by * 128 + tx * 8;
    float qi[8], qj[8];
#pragma unroll
    for (int m = 0; m < 8; m++) qi[m] = g_qnorm[gi0 + m];
#pragma unroll
    for (int n = 0; n < 8; n++) qj[n] = g_qnorm[gj0 + n];
#pragma unroll
    for (int m = 0; m < 8; m++) {
#pragma unroll
        for (int n = 0; n < 8; n++) {
            float dv = fmaxf(qi[m] + qj[n] - 2.0f * acc[m][n], 0.0f);
            g_D[(size_t)(gi0 + m) * NQ + (gj0 + n)] = dv;
            g_D[(size_t)(gj0 + n) * NQ + (gi0 + m)] = dv;
        }
    }
}

// ------------------------------ top-13 per row (unchanged) --------------------------
__global__ void __launch_bounds__(256) topk_kernel() {
    int row = blockIdx.x;
    int tid = threadIdx.x;
    __shared__ float s[NQ];
    __shared__ unsigned long long red[256];
    const float* drow = &g_D[(size_t)row * NQ];
    for (int j = tid; j < NQ; j += 256) s[j] = sqrtf(drow[j]);
    __syncthreads();
    for (int sel = 0; sel < KNN + 1; sel++) {
        unsigned long long best = ~0ull;
        for (int j = tid; j < NQ; j += 256) {
            unsigned long long key =
                ((unsigned long long)__float_as_uint(s[j]) << 32) | (unsigned)j;
            best = best < key ? best : key;
        }
        red[tid] = best;
        __syncthreads();
        for (int o = 128; o > 0; o >>= 1) {
            if (tid < o) red[tid] = red[tid] < red[tid + o] ? red[tid] : red[tid + o];
            __syncthreads();
        }
        if (tid == 0) {
            unsigned long long b = red[0];
            int idx = (int)(b & 0xffffffffull);
            float val = __uint_as_float((unsigned)(b >> 32));
            if (sel >= 1) {
                g_nbrs[row * KNN + sel - 1] = idx;
                g_wdist[row * KNN + sel - 1] = val;
            }
            if (sel == KNN) g_sigma[row] = val + 1e-8f;
            s[idx] = FLT_MAX;
        }
        __syncthreads();
    }
}

// ------------------------------ fused CSR build: deg+scan+fill+sort+Dinv ------------
__global__ void __launch_bounds__(1024) graph_kernel() {
    __shared__ int sdeg[NQ];     // 16KB
    __shared__ int scur[NQ];     // 16KB
    __shared__ int ssum[1024];   // 4KB
    int tid = threadIdx.x;
    for (int i = tid; i < NQ; i += 1024) sdeg[i] = 0;
    __syncthreads();
    for (int idx = tid; idx < NQ * KNN; idx += 1024) {
        int i = idx / KNN;
        int j = g_nbrs[idx];
        atomicAdd(&sdeg[i], 1);
        atomicAdd(&sdeg[j], 1);
    }
    __syncthreads();
    int b = tid * 4;
    int d0 = sdeg[b], d1 = sdeg[b + 1], d2 = sdeg[b + 2], d3 = sdeg[b + 3];
    ssum[tid] = d0 + d1 + d2 + d3;
    __syncthreads();
    for (int off = 1; off < 1024; off <<= 1) {
        int v = (tid >= off) ? ssum[tid - off] : 0;
        __syncthreads();
        ssum[tid] += v;
        __syncthreads();
    }
    int excl = (tid == 0) ? 0 : ssum[tid - 1];
    g_rowptr[b] = excl;     scur[b] = excl;     excl += d0;
    g_rowptr[b + 1] = excl; scur[b + 1] = excl; excl += d1;
    g_rowptr[b + 2] = excl; scur[b + 2] = excl; excl += d2;
    g_rowptr[b + 3] = excl; scur[b + 3] = excl; excl += d3;
    if (tid == 1023) g_rowptr[NQ] = excl;
    __syncthreads();
    for (int idx = tid; idx < NQ * KNN; idx += 1024) {
        int i = idx / KNN;
        int j = g_nbrs[idx];
        float w = expf(-g_wdist[idx] / (g_sigma[i] * g_sigma[j]));
        float h = 0.5f * w;
        int p1 = atomicAdd(&scur[i], 1);
        g_col[p1] = j; g_val[p1] = h;
        int p2 = atomicAdd(&scur[j], 1);
        g_col[p2] = i; g_val[p2] = h;
    }
    __syncthreads();
    // sort each row by column (duplicate columns carry identical values) + Dinv
    for (int row = tid; row < NQ; row += 1024) {
        int s = g_rowptr[row], e = g_rowptr[row + 1];
        for (int i2 = s + 1; i2 < e; i2++) {
            int c = g_col[i2]; float v = g_val[i2];
            int j2 = i2 - 1;
            while (j2 >= s && g_col[j2] > c) {
                g_col[j2 + 1] = g_col[j2]; g_val[j2 + 1] = g_val[j2]; j2--;
            }
            g_col[j2 + 1] = c; g_val[j2 + 1] = v;
        }
        float sum = 0.f;
        for (int i2 = s; i2 < e; i2++) sum += g_val[i2];
        g_Dinv[row] = 1.0f / (sum + 1e-8f);
    }
}

// ------------------------------ a = sqdist(q, protos), d2 = a.min(1): 8 rows/block --
__global__ void __launch_bounds__(256) a_kernel(const float* __restrict__ q) {
    int r0 = blockIdx.x * 8;
    int tid = threadIdx.x, w = tid >> 5, lane = tid & 31;
    __shared__ float qs[8][DIM];    // 32KB
    __shared__ float wmin[8][8];    // [row][warp]
    for (int i = tid; i < 8 * DIM; i += 256)
        qs[i >> 10][i & (DIM - 1)] = q[(size_t)r0 * DIM + i];
    __syncthreads();
    float lmin[8];
#pragma unroll
    for (int r = 0; r < 8; r++) lmin[r] = FLT_MAX;
    for (int pi = 0; pi < 8; pi++) {
        int p = w * 8 + pi;
        const float* pr = &g_protos[p * DIM];
        float dot[8];
#pragma unroll
        for (int r = 0; r < 8; r++) dot[r] = 0.f;
        for (int d = lane; d < DIM; d += 32) {
            float pv = pr[d];
#pragma unroll
            for (int r = 0; r < 8; r++) dot[r] += qs[r][d] * pv;
        }
#pragma unroll
        for (int r = 0; r < 8; r++) dot[r] = warpSumf(dot[r]);
        float pn = g_pnorm[p];
#pragma unroll
        for (int r = 0; r < 8; r++) {
            float av = fmaxf(g_qnorm[r0 + r] + pn - 2.0f * dot[r], 0.0f);
            if (lane == 0) g_a[(r0 + r) * NC + p] = av;
            lmin[r] = fminf(lmin[r], av);
        }
    }
    if (lane == 0)
#pragma unroll
        for (int r = 0; r < 8; r++) wmin[r][w] = lmin[r];
    __syncthreads();
    if (tid < 8) {
        float m = wmin[tid][0];
#pragma unroll
        for (int ww = 1; ww < 8; ww++) m = fminf(m, wmin[tid][ww]);
        g_d2[r0 + tid] = m;
    }
}

// ------------------------------ median (bitonic) + coef fused -----------------------
__global__ void __launch_bounds__(1024) median_kernel() {
    __shared__ float sd[NQ];
    __shared__ float smed2;
    int tid = threadIdx.x;
    for (int j = tid; j < NQ; j += 1024) sd[j] = sqrtf(g_d2[j]);
    __syncthreads();
    for (int k = 2; k <= NQ; k <<= 1) {
        for (int j = k >> 1; j > 0; j >>= 1) {
            for (int i = tid; i < NQ; i += 1024) {
                int l = i ^ j;
                if (l > i) {
                    bool asc = ((i & k) == 0);
                    float a = sd[i], b = sd[l];
                    if ((a > b) == asc) { sd[i] = b; sd[l] = a; }
                }
            }
            __syncthreads();
        }
    }
    if (tid == 0) {
        float med = 0.5f * (sd[NQ / 2 - 1] + sd[NQ / 2]);
        smed2 = 2.0f * med * med + 1e-8f;
    }
    __syncthreads();
    float m2 = smed2;
    for (int i = tid; i < NQ; i += 1024)
        g_coef[i] = expf(-g_d2[i] / m2) * g_Dinv[i];
}

// ------------------------------ persistent iteration kernel -------------------------
__device__ __forceinline__ void grid_barrier(int sense) {
    __threadfence();
    __syncthreads();
    if (threadIdx.x == 0) {
        if (atomicAdd(&g_barc, 1) == IBLK - 1) {
            g_barc = 0;
            __threadfence();
            g_bars = sense;
        } else {
            while (g_bars != sense) { }
        }
    }
    __syncthreads();
}

__global__ void __launch_bounds__(256) iter_kernel(float* __restrict__ out) {
    int tid = threadIdx.x, w = tid >> 5, lane = tid & 31;
    int r0 = blockIdx.x * RPB + w * 4;     // each warp owns 4 rows
    __shared__ unsigned sdiff[8];
    __shared__ int sconv;

    float yp0[4], yp1[4], yc0[4], yc1[4];
    float ar0[4], ar1[4], cf[4];
    int rs[4], re[4];

    // ---- load constants + y0 = softmax(-a) ----
#pragma unroll
    for (int r = 0; r < 4; r++) {
        int row = r0 + r;
        ar0[r] = g_a[row * NC + lane];
        ar1[r] = g_a[row * NC + lane + 32];
        cf[r] = g_coef[row];
        rs[r] = g_rowptr[row];
        re[r] = g_rowptr[row + 1];
        float l0 = -ar0[r], l1 = -ar1[r];
        float m = warpMaxf(fmaxf(l0, l1));
        float e0 = expf(l0 - m), e1 = expf(l1 - m);
        float ss = warpSumf(e0 + e1);
        yp0[r] = e0 / ss; yp1[r] = e1 / ss;
        g_Y[0][row * NC + lane] = yp0[r];
        g_Y[0][row * NC + lane + 32] = yp1[r];
        yc0[r] = yp0[r]; yc1[r] = yp1[r];
    }
    int sense = 1;
    grid_barrier(sense);

    int converged = 0;
    for (int t = 0; t < MAX_ITER; t++) {
        const float* __restrict__ yin = g_Y[t & 1];
        float* __restrict__ yout = g_Y[(t + 1) & 1];
        float dmx = 0.f;
#pragma unroll
        for (int r = 0; r < 4; r++) {
            int row = r0 + r;
            float acc0 = 0.f, acc1 = 0.f;
            for (int k = rs[r]; k < re[r]; k++) {
                int c = g_col[k];
                float v = g_val[k];
                acc0 += v * __ldcg(&yin[c * NC + lane]);
                acc1 += v * __ldcg(&yin[c * NC + lane + 32]);
            }
            float l0 = cf[r] * acc0 - ar0[r];
            float l1 = cf[r] * acc1 - ar1[r];
            float m = warpMaxf(fmaxf(l0, l1));
            float e0 = expf(l0 - m), e1 = expf(l1 - m);
            float ss = warpSumf(e0 + e1);
            yc0[r] = e0 / ss; yc1[r] = e1 / ss;
            dmx = fmaxf(dmx, fmaxf(fabsf(yc0[r] - yp0[r]), fabsf(yc1[r] - yp1[r])));
            yout[row * NC + lane] = yc0[r];
            yout[row * NC + lane + 32] = yc1[r];
        }
        dmx = warpMaxf(dmx);
        if (lane == 0) sdiff[w] = __float_as_uint(dmx);
        __syncthreads();
        if (tid == 0) {
            unsigned mx = 0;
            for (int i = 0; i < 8; i++) mx = max(mx, sdiff[i]);
            if (__uint_as_float(mx) >= EPS_CONV) g_flag[t] = 1;
        }
        sense++;
        grid_barrier(sense);
        if (tid == 0) sconv = *(volatile int*)&g_flag[t];
        __syncthreads();
        if (sconv == 0) { converged = 1; break; }   // answer is y_t (in yp regs)
#pragma unroll
        for (int r = 0; r < 4; r++) { yp0[r] = yc0[r]; yp1[r] = yc1[r]; }
    }

    // ---- argmax of the answer (own rows; held in registers) ----
#pragma unroll
    for (int r = 0; r < 4; r++) {
        float v0 = converged ? yp0[r] : yc0[r];
        float v1 = converged ? yp1[r] : yc1[r];
        float bv; int bi;
        if (v0 >= v1) { bv = v0; bi = lane; } else { bv = v1; bi = lane + 32; }
#pragma unroll
        for (int o = 16; o > 0; o >>= 1) {
            float ov = __shfl_xor_sync(0xffffffffu, bv, o);
            int oi = __shfl_xor_sync(0xffffffffu, bi, o);
            if (ov > bv || (ov == bv && oi < bi)) { bv = ov; bi = oi; }
        }
        if (lane == 0) out[r0 + r] = (float)bi;
    }
}

// ------------------------------ launch ----------------------------------------------
extern "C" void kernel_launch(void* const* d_in, const int* in_sizes, int n_in,
                              void* d_out, int out_size) {
    // Rank-based identification: smallest -> y_s, middle -> feat_s, largest -> feat_q.
    int i0 = 0, i1 = 1, i2 = 2;
    if (n_in >= 3) {
        int idxs[3] = {0, 1, 2};
        for (int a = 0; a < 2; a++)
            for (int b = a + 1; b < 3; b++)
                if ((long long)in_sizes[idxs[b]] < (long long)in_sizes[idxs[a]]) {
                    int tmp = idxs[a]; idxs[a] = idxs[b]; idxs[b] = tmp;
                }
        i0 = idxs[0]; i1 = idxs[1]; i2 = idxs[2];
    }
    const void*  y_s    = d_in[i0];
    const float* feat_s = (const float*)d_in[i1];
    const float* feat_q = (const float*)d_in[i2];

    init_kernel<<<1, 256>>>((const unsigned*)y_s);
    protos_kernel<<<NC, 256>>>(feat_s, y_s);
    qnorm_kernel<<<NQ / 8, 256>>>(feat_q);
    dim3 gg(NQ / 128, NQ / 128);
    gemm_dist_kernel<<<gg, 256>>>(feat_q);
    topk_kernel<<<NQ, 256>>>();
    graph_kernel<<<1, 1024>>>();
    a_kernel<<<NQ / 8, 256>>>(feat_q);
    median_kernel<<<1, 1024>>>();
    iter_kernel<<<IBLK, 256>>>((float*)d_out);
}